// round 11
// baseline (speedup 1.0000x reference)
#include <cuda_runtime.h>
#include <math_constants.h>

#define V  50000
#define E  300
#define H  256
#define R  2048
#define L0 128
#define LR 64
#define S  2049          // 1 + R
#define G3 768           // 3*H

#define NC     8         // CTAs in the single cluster (handles BOTH directions)
#define DPC    32        // h-dims per CTA per direction
#define GRU_T  384       // 12 warps x (8 rows dir0 + 8 rows dir1)

// ---------------- scratch (device globals; no allocation allowed) -------------
__device__ float g_X[S * E];
__device__ float g_gi_f[S * G3];
__device__ float g_gi_b[S * G3];
__device__ float g_ys_f[S * H];
__device__ float g_ys_b[S * H];

// ---------------- small PTX helpers ------------------------------------------
__device__ __forceinline__ unsigned long long pk2(float lo, float hi) {
    unsigned long long r;
    asm("mov.b64 %0, {%1, %2};" : "=l"(r) : "f"(lo), "f"(hi));
    return r;
}
__device__ __forceinline__ float unpk_sum(unsigned long long v) {
    float a, b;
    asm("mov.b64 {%0, %1}, %2;" : "=f"(a), "=f"(b) : "l"(v));
    return a + b;
}
__device__ __forceinline__ unsigned long long ffma2(unsigned long long a,
                                                    unsigned long long b,
                                                    unsigned long long c) {
    unsigned long long d;
    asm("fma.rn.f32x2 %0, %1, %2, %3;" : "=l"(d) : "l"(a), "l"(b), "l"(c));
    return d;
}
__device__ __forceinline__ unsigned smem_u32(const void* p) {
    return (unsigned)__cvta_generic_to_shared(p);
}
__device__ __forceinline__ void mbar_init(unsigned addr, unsigned count) {
    asm volatile("mbarrier.init.shared.b64 [%0], %1;" :: "r"(addr), "r"(count) : "memory");
}
__device__ __forceinline__ void mbar_wait_cluster(unsigned addr, unsigned parity) {
    unsigned done;
    do {
        asm volatile(
            "{\n\t.reg .pred p;\n\t"
            "mbarrier.try_wait.parity.acquire.cluster.shared::cta.b64 p, [%1], %2, 0x989680;\n\t"
            "selp.b32 %0, 1, 0, p;\n\t}"
            : "=r"(done) : "r"(addr), "r"(parity) : "memory");
    } while (!done);
}
__device__ __forceinline__ unsigned cluster_rank() {
    unsigned r;
    asm("mov.u32 %0, %%cluster_ctarank;" : "=r"(r));
    return r;
}
__device__ __forceinline__ unsigned mapa_u32(unsigned addr, unsigned rank) {
    unsigned rem;
    asm("mapa.shared::cluster.u32 %0, %1, %2;" : "=r"(rem) : "r"(addr), "r"(rank));
    return rem;
}
__device__ __forceinline__ void st_cluster_f32(unsigned addr, float v) {
    asm volatile("st.shared::cluster.f32 [%0], %1;" :: "r"(addr), "f"(v) : "memory");
}
// plain (non-release) remote arrive — the R4-verified fast path
__device__ __forceinline__ void mbar_arrive_remote(unsigned addr) {
    asm volatile("mbarrier.arrive.shared::cluster.b64 _, [%0];" :: "r"(addr) : "memory");
}
__device__ __forceinline__ void cluster_sync() {
    asm volatile("barrier.cluster.arrive.aligned;" ::: "memory");
    asm volatile("barrier.cluster.wait.aligned;" ::: "memory");
}
__device__ __forceinline__ void bar_arrive_n(int id) {
    asm volatile("bar.arrive %0, %1;" :: "r"(id), "r"(GRU_T) : "memory");
}
__device__ __forceinline__ void bar_sync_n(int id) {
    asm volatile("bar.sync %0, %1;" :: "r"(id), "r"(GRU_T) : "memory");
}
__device__ __forceinline__ float fsigmoid(float x) {
    return __fdividef(1.f, 1.f + __expf(-x));
}
__device__ __forceinline__ float ftanh_fast(float x) {
    return __fdividef(2.f, 1.f + __expf(-2.f * x)) - 1.f;
}

// ---------------- kernel 1: embedding sums -> X -------------------------------
__global__ void embed_kernel(const int* __restrict__ orig,
                             const int* __restrict__ reply,
                             const int* __restrict__ lens,
                             const float* __restrict__ embed) {
    int t = blockIdx.x;
    int e = threadIdx.x;
    if (e >= E) return;
    float acc = 0.f;
    if (t == 0) {
        #pragma unroll 4
        for (int l = 0; l < L0; ++l) {
            int tok = orig[l];
            acc += embed[(long long)tok * E + e];
        }
    } else {
        int r = t - 1;
        int len = lens[r];
        const int* rt = reply + r * LR;
        #pragma unroll 4
        for (int l = 0; l < len; ++l) {
            int tok = rt[l];
            acc += embed[(long long)tok * E + e];
        }
    }
    g_X[t * E + e] = acc;
}

// ---------------- kernel 2: gi GEMMs (both directions) ------------------------
#define TT 32
#define RR 64
#define KC 32
__global__ void gi_kernel(const float* __restrict__ Wf, const float* __restrict__ bf,
                          const float* __restrict__ Wb, const float* __restrict__ bb) {
    int dir = blockIdx.z;
    const float* W    = dir ? Wb : Wf;
    const float* bias = dir ? bb : bf;
    float* out        = dir ? g_gi_b : g_gi_f;
    int t0 = blockIdx.x * TT;
    int r0 = blockIdx.y * RR;

    __shared__ float Xs[TT][KC];
    __shared__ float Ws[RR][KC + 1];

    int tid = threadIdx.x;
    int r  = tid % RR;
    int tg = tid / RR;

    float acc[8];
    #pragma unroll
    for (int j = 0; j < 8; ++j) acc[j] = 0.f;

    for (int kk = 0; kk < E; kk += KC) {
        for (int i = tid; i < RR * KC; i += 256) {
            int rr = i / KC, k = i % KC;
            Ws[rr][k] = (kk + k < E) ? W[(r0 + rr) * E + kk + k] : 0.f;
        }
        for (int i = tid; i < TT * KC; i += 256) {
            int ttl = i / KC, k = i % KC;
            int t = t0 + ttl;
            float v = 0.f;
            if (t < S && kk + k < E) {
                int tsrc = dir ? (S - 1 - t) : t;
                v = g_X[tsrc * E + kk + k];
            }
            Xs[ttl][k] = v;
        }
        __syncthreads();
        #pragma unroll
        for (int k = 0; k < KC; ++k) {
            float wv = Ws[r][k];
            #pragma unroll
            for (int j = 0; j < 8; ++j)
                acc[j] += wv * Xs[tg * 8 + j][k];
        }
        __syncthreads();
    }
    float bv = bias[r0 + r];
    #pragma unroll
    for (int j = 0; j < 8; ++j) {
        int t = t0 + tg * 8 + j;
        if (t < S) out[t * G3 + r0 + r] = acc[j] + bv;
    }
}

// ---------------- kernel 3: GRU, BOTH directions interleaved in one cluster ---
// Single 8-CTA cluster. CTA c owns dims [32c,32c+32) of BOTH directions.
// 12 warps; per dir, warp w owns local rows 8w..8w+7 (R4 layout/protocol).
// Iteration t: [wait d0] dot0 reduce STS -> bar1 -> warp0 funnel0 (gates,
// publish to 8 peers, 8 plain arrives) ; [wait d1] dot1 ... bar2 -> funnel1.
// While dir0's publish crosses the NoC, the CTA computes dir1's full phase
// (and vice versa) -> both waits are satisfied on arrival; the pair cost is
// pure issue/compute. Double-buffered h + parity barriers per direction.
__global__ void __launch_bounds__(GRU_T, 1) __cluster_dims__(NC, 1, 1)
gru_kernel(const float* __restrict__ Whh_f, const float* __restrict__ bhh_f,
           const float* __restrict__ Whh_b, const float* __restrict__ bhh_b) {
    unsigned c = cluster_rank();
    int tid  = threadIdx.x;
    int w    = tid >> 5;        // 0..11
    int lane = tid & 31;
    int base = (int)c * DPC;

    __shared__ __align__(16) float hbuf[2][2][H];   // [dir][parity][dim]
    __shared__ float s_gh[2][96];                   // [dir][row]
    __shared__ __align__(8) unsigned long long bars[4];  // [dir*2+parity]

    unsigned hbuf_u32 = smem_u32(&hbuf[0][0][0]);
    unsigned bars_u32 = smem_u32(&bars[0]);

    if (tid == 0) {
        mbar_init(bars_u32,      NC);   // dir0 parity0
        mbar_init(bars_u32 + 8,  NC);   // dir0 parity1
        mbar_init(bars_u32 + 16, NC);   // dir1 parity0
        mbar_init(bars_u32 + 24, NC);   // dir1 parity1
    }
    if (tid < H) { hbuf[0][0][tid] = 0.f; hbuf[1][0][tid] = 0.f; }
    __syncthreads();
    cluster_sync();   // peers must not arrive on an uninitialized mbarrier

    // resident weights: [dir*8+k][4] — 8 rows x 8 cols per lane per dir
    unsigned long long w2[16][4];
    #pragma unroll
    for (int d = 0; d < 2; ++d) {
        const float* Whh = d ? Whh_b : Whh_f;
        #pragma unroll
        for (int k = 0; k < 8; ++k) {
            int lr = w * 8 + k;
            int row = (lr >> 5) * H + base + (lr & 31);
            const float* wr = Whh + (size_t)row * H + lane * 8;
            float4 a = *(const float4*)wr;
            float4 b = *(const float4*)(wr + 4);
            w2[d * 8 + k][0] = pk2(a.x, a.y); w2[d * 8 + k][1] = pk2(a.z, a.w);
            w2[d * 8 + k][2] = pk2(b.x, b.y); w2[d * 8 + k][3] = pk2(b.z, b.w);
        }
    }
    // bias for the row slot this lane owns after the fold reduce (per dir)
    float breg0, breg1;
    {
        int lrb = w * 8 + (lane & 7);
        int rowb = (lrb >> 5) * H + base + (lrb & 31);
        breg0 = bhh_f[rowb];
        breg1 = bhh_b[rowb];
    }

    // warp0 per-lane gate state (lane = local dim), per dir
    float g0r = 0.f, g0z = 0.f, g0n = 0.f, hold0 = 0.f;
    float g1r = 0.f, g1z = 0.f, g1n = 0.f, hold1 = 0.f;
    if (w == 0) {
        int ii = base + lane;
        g0r = g_gi_f[ii]; g0z = g_gi_f[H + ii]; g0n = g_gi_f[2 * H + ii];
        g1r = g_gi_b[ii]; g1z = g_gi_b[H + ii]; g1n = g_gi_b[2 * H + ii];
    }

    unsigned ph[4] = {0u, 0u, 0u, 0u};
    const unsigned FM = 0xffffffffu;

    for (int t = 0; t < S; ++t) {
        int par  = t & 1;
        int npar = (t + 1) & 1;
        bool haveNext = (t + 1 < S);

        // prefetch gi for step t+1, both dirs (warp 0; hidden under dot phases)
        float n0r = 0.f, n0z = 0.f, n0n = 0.f;
        float n1r = 0.f, n1z = 0.f, n1n = 0.f;
        if (w == 0 && haveNext) {
            int o = (t + 1) * G3 + base + lane;
            n0r = __ldg(g_gi_f + o); n0z = __ldg(g_gi_f + o + H); n0n = __ldg(g_gi_f + o + 2 * H);
            n1r = __ldg(g_gi_b + o); n1z = __ldg(g_gi_b + o + H); n1n = __ldg(g_gi_b + o + 2 * H);
        }

        #pragma unroll
        for (int d = 0; d < 2; ++d) {
            // ---- wait for h_t of dir d ----
            if (t) {
                int bidx = d * 2 + par;
                mbar_wait_cluster(bars_u32 + bidx * 8, ph[bidx]);
                ph[bidx] ^= 1;
            }

            // ---- dot: 8 rows x 8 cols per lane (dir d) ----
            const ulonglong2* hp =
                (const ulonglong2*)(&hbuf[d][par][lane * 8]);
            ulonglong2 ha = hp[0];
            ulonglong2 hb = hp[1];
            unsigned long long h2[4];
            h2[0] = ha.x; h2[1] = ha.y; h2[2] = hb.x; h2[3] = hb.y;

            float p[8];
            #pragma unroll
            for (int k = 0; k < 8; ++k) {
                unsigned long long acc = ffma2(w2[d * 8 + k][0], h2[0], 0ULL);
                acc = ffma2(w2[d * 8 + k][1], h2[1], acc);
                acc = ffma2(w2[d * 8 + k][2], h2[2], acc);
                acc = ffma2(w2[d * 8 + k][3], h2[3], acc);
                p[k] = unpk_sum(acc);
            }

            // ---- fold reduce -> lane l<8 holds row 8w+l ----
            bool b0 = (lane & 1), b1 = (lane & 2), b2 = (lane & 4);
            float q0, q1, q2, q3, r0v, r1v, u;
            { float v = b0 ? p[0] : p[1]; float sx = __shfl_xor_sync(FM, v, 1);
              q0 = (b0 ? p[1] : p[0]) + sx; }
            { float v = b0 ? p[2] : p[3]; float sx = __shfl_xor_sync(FM, v, 1);
              q1 = (b0 ? p[3] : p[2]) + sx; }
            { float v = b0 ? p[4] : p[5]; float sx = __shfl_xor_sync(FM, v, 1);
              q2 = (b0 ? p[5] : p[4]) + sx; }
            { float v = b0 ? p[6] : p[7]; float sx = __shfl_xor_sync(FM, v, 1);
              q3 = (b0 ? p[7] : p[6]) + sx; }
            { float v = b1 ? q0 : q1; float sx = __shfl_xor_sync(FM, v, 2);
              r0v = (b1 ? q1 : q0) + sx; }
            { float v = b1 ? q2 : q3; float sx = __shfl_xor_sync(FM, v, 2);
              r1v = (b1 ? q3 : q2) + sx; }
            { float v = b2 ? r0v : r1v; float sx = __shfl_xor_sync(FM, v, 4);
              u = (b2 ? r1v : r0v) + sx; }
            u += __shfl_xor_sync(FM, u, 8);
            u += __shfl_xor_sync(FM, u, 16);
            if (lane < 8) s_gh[d][w * 8 + lane] = u + (d ? breg1 : breg0);

            // ---- funnel (warp 0) / arrive (warps 1-11) ----
            if (w != 0) {
                bar_arrive_n(1 + d);
            } else {
                bar_sync_n(1 + d);     // all 12 warps' STS visible (BAR drains)
                float ghr = s_gh[d][lane];
                float ghz = s_gh[d][32 + lane];
                float ghn = s_gh[d][64 + lane];
                float gr = d ? g1r : g0r;
                float gz = d ? g1z : g0z;
                float gn = d ? g1n : g0n;
                float ho = d ? hold1 : hold0;
                float rr = fsigmoid(gr + ghr);
                float zz = fsigmoid(gz + ghz);
                float nn = ftanh_fast(gn + rr * ghn);
                float hn = (1.f - zz) * nn + zz * ho;
                if (d) hold1 = hn; else hold0 = hn;

                // publish h_{t+1}(dir d) to all 8 CTAs + 8 plain arrives
                if (haveNext) {
                    unsigned off = hbuf_u32
                        + (unsigned)(d * 2 * H * 4 + npar * H * 4 + (base + lane) * 4);
                    #pragma unroll
                    for (int r = 0; r < NC; ++r)
                        st_cluster_f32(mapa_u32(off, (unsigned)r), hn);
                    __syncwarp();
                    if (lane < NC)
                        mbar_arrive_remote(
                            mapa_u32(bars_u32 + (unsigned)((d * 2 + npar) * 8),
                                     (unsigned)lane));
                }

                // ys store
                if (d) g_ys_b[(S - 1 - t) * H + base + lane] = hn;
                else   g_ys_f[t * H + base + lane] = hn;
            }
        }

        if (w == 0) {
            g0r = n0r; g0z = n0z; g0n = n0n;
            g1r = n1r; g1z = n1z; g1n = n1n;
        }
    }
    cluster_sync();
}

// ---------------- kernel 4: output projection --------------------------------
#define OTT 16
__global__ void outproj_kernel(const float* __restrict__ Wl,
                               const float* __restrict__ bl,
                               float* __restrict__ outbuf) {
    int t0 = blockIdx.x * OTT;
    int j0 = blockIdx.y * RR;
    __shared__ float As[OTT][KC];
    __shared__ float Ws[RR][KC + 1];
    int tid = threadIdx.x;
    int r  = tid % RR;
    int tg = tid / RR;
    float acc[4];
    #pragma unroll
    for (int j = 0; j < 4; ++j) acc[j] = 0.f;

    for (int kk = 0; kk < 2 * H; kk += KC) {
        const float* ysrc = (kk < H) ? g_ys_f : g_ys_b;
        int kbase = (kk < H) ? kk : (kk - H);
        for (int i = tid; i < RR * KC; i += 256) {
            int rr = i / KC, k = i % KC;
            Ws[rr][k] = Wl[(j0 + rr) * (2 * H) + kk + k];
        }
        for (int i = tid; i < OTT * KC; i += 256) {
            int ttl = i / KC, k = i % KC;
            int t = t0 + ttl;
            As[ttl][k] = (t < S) ? ysrc[t * H + kbase + k] : 0.f;
        }
        __syncthreads();
        #pragma unroll
        for (int k = 0; k < KC; ++k) {
            float wv = Ws[r][k];
            #pragma unroll
            for (int j = 0; j < 4; ++j)
                acc[j] += wv * As[tg * 4 + j][k];
        }
        __syncthreads();
    }
    float bv = bl[j0 + r];
    #pragma unroll
    for (int j = 0; j < 4; ++j) {
        int t = t0 + tg * 4 + j;
        if (t < S) outbuf[t * H + j0 + r] = acc[j] + bv;
    }
}

// ---------------- kernel 5: attention + final head (single block) -------------
__global__ void attn_kernel(const float* __restrict__ outbuf,
                            const float* __restrict__ Wo,
                            const float* __restrict__ bo,
                            const float* __restrict__ label,
                            float* __restrict__ tail) {
    __shared__ float s_hsum[H];
    __shared__ float s_w[S];
    __shared__ float s_red[32];
    __shared__ float s_ctx[4][H];

    int tid = threadIdx.x;
    int wp  = tid >> 5;
    int ln  = tid & 31;

    if (tid < H) s_hsum[tid] = g_ys_f[(S - 1) * H + tid] + g_ys_b[tid];
    __syncthreads();

    for (int t = wp; t < S; t += 32) {
        const float* o = outbuf + t * H;
        float s = 0.f;
        #pragma unroll
        for (int k = ln; k < H; k += 32) s += o[k] * s_hsum[k];
        s += __shfl_down_sync(0xffffffffu, s, 16);
        s += __shfl_down_sync(0xffffffffu, s, 8);
        s += __shfl_down_sync(0xffffffffu, s, 4);
        s += __shfl_down_sync(0xffffffffu, s, 2);
        s += __shfl_down_sync(0xffffffffu, s, 1);
        if (ln == 0) s_w[t] = s;
    }
    __syncthreads();

    float m = -CUDART_INF_F;
    for (int t = tid; t < S; t += 1024) m = fmaxf(m, s_w[t]);
    for (int off = 16; off >= 1; off >>= 1)
        m = fmaxf(m, __shfl_down_sync(0xffffffffu, m, off));
    if (ln == 0) s_red[wp] = m;
    __syncthreads();
    if (tid < 32) {
        float mm = s_red[tid];
        for (int off = 16; off >= 1; off >>= 1)
            mm = fmaxf(mm, __shfl_down_sync(0xffffffffu, mm, off));
        if (tid == 0) s_red[0] = mm;
    }
    __syncthreads();
    float M = s_red[0];
    __syncthreads();

    float lsum = 0.f;
    for (int t = tid; t < S; t += 1024) {
        float e = expf(s_w[t] - M);
        s_w[t] = e;
        lsum += e;
    }
    for (int off = 16; off >= 1; off >>= 1)
        lsum += __shfl_down_sync(0xffffffffu, lsum, off);
    if (ln == 0) s_red[wp] = lsum;
    __syncthreads();
    if (tid < 32) {
        float ss = s_red[tid];
        for (int off = 16; off >= 1; off >>= 1)
            ss += __shfl_down_sync(0xffffffffu, ss, off);
        if (tid == 0) s_red[0] = ss;
    }
    __syncthreads();
    float SUM = s_red[0];

    int j    = tid & 255;
    int part = tid >> 8;
    float cacc = 0.f;
    #pragma unroll 4
    for (int t = part; t < S; t += 4) cacc += s_w[t] * outbuf[t * H + j];
    s_ctx[part][j] = cacc;
    __syncthreads();

    if (tid < H) {
        float cj = (s_ctx[0][tid] + s_ctx[1][tid] + s_ctx[2][tid] + s_ctx[3][tid]) / SUM;
        s_hsum[tid] = cj * Wo[tid];
    }
    __syncthreads();

    if (tid < 32) {
        float a = 0.f;
        #pragma unroll
        for (int q = 0; q < 8; ++q) a += s_hsum[tid + q * 32];
        for (int off = 16; off >= 1; off >>= 1)
            a += __shfl_down_sync(0xffffffffu, a, off);
        if (tid == 0) {
            float res = 1.f / (1.f + expf(-(a + bo[0])));
            float d = label[0] - res;
            tail[0] = d * d;
            tail[1] = res;
        }
    }
}

// ---------------- launch ------------------------------------------------------
extern "C" void kernel_launch(void* const* d_in, const int* in_sizes, int n_in,
                              void* d_out, int out_size) {
    const int*   orig   = (const int*)d_in[0];
    const int*   reply  = (const int*)d_in[1];
    const int*   lens   = (const int*)d_in[2];
    const float* label  = (const float*)d_in[3];
    const float* embed  = (const float*)d_in[4];
    const float* Wih_f  = (const float*)d_in[5];
    const float* Whh_f  = (const float*)d_in[6];
    const float* bih_f  = (const float*)d_in[7];
    const float* bhh_f  = (const float*)d_in[8];
    const float* Wih_b  = (const float*)d_in[9];
    const float* Whh_b  = (const float*)d_in[10];
    const float* bih_b  = (const float*)d_in[11];
    const float* bhh_b  = (const float*)d_in[12];
    const float* Wl     = (const float*)d_in[13];
    const float* bl     = (const float*)d_in[14];
    const float* Wo     = (const float*)d_in[15];
    const float* bo     = (const float*)d_in[16];
    float* out = (float*)d_out;

    embed_kernel<<<S, 320>>>(orig, reply, lens, embed);

    dim3 gi_grid((S + TT - 1) / TT, G3 / RR, 2);
    gi_kernel<<<gi_grid, 256>>>(Wih_f, bih_f, Wih_b, bih_b);

    gru_kernel<<<NC, GRU_T>>>(Whh_f, bhh_f, Whh_b, bhh_b);

    dim3 op_grid((S + OTT - 1) / OTT, H / RR);   // 129 x 4
    outproj_kernel<<<op_grid, 256>>>(Wl, bl, out);

    attn_kernel<<<1, 1024>>>(out, Wo, bo, label, out + S * H);
}

// round 12
// speedup vs baseline: 1.6802x; 1.6802x over previous
#include <cuda_runtime.h>
#include <math_constants.h>

#define V  50000
#define E  300
#define H  256
#define R  2048
#define L0 128
#define LR 64
#define S  2049          // 1 + R
#define G3 768           // 3*H

#define NC     8         // CTAs per cluster (one cluster per direction)
#define DPC    32        // h-dims per CTA
#define GRU_T  256       // 8 warps x 12 rows = 96 rows per CTA

// ---------------- scratch (device globals; no allocation allowed) -------------
__device__ float g_X[S * E];
__device__ float g_gi_f[S * G3];
__device__ float g_gi_b[S * G3];
__device__ float g_ys_f[S * H];
__device__ float g_ys_b[S * H];

// ---------------- small PTX helpers ------------------------------------------
__device__ __forceinline__ unsigned long long pk2(float lo, float hi) {
    unsigned long long r;
    asm("mov.b64 %0, {%1, %2};" : "=l"(r) : "f"(lo), "f"(hi));
    return r;
}
__device__ __forceinline__ float unpk_sum(unsigned long long v) {
    float a, b;
    asm("mov.b64 {%0, %1}, %2;" : "=f"(a), "=f"(b) : "l"(v));
    return a + b;
}
__device__ __forceinline__ unsigned long long ffma2(unsigned long long a,
                                                    unsigned long long b,
                                                    unsigned long long c) {
    unsigned long long d;
    asm("fma.rn.f32x2 %0, %1, %2, %3;" : "=l"(d) : "l"(a), "l"(b), "l"(c));
    return d;
}
__device__ __forceinline__ unsigned smem_u32(const void* p) {
    return (unsigned)__cvta_generic_to_shared(p);
}
__device__ __forceinline__ void mbar_init(unsigned addr, unsigned count) {
    asm volatile("mbarrier.init.shared.b64 [%0], %1;" :: "r"(addr), "r"(count) : "memory");
}
__device__ __forceinline__ void mbar_wait_cluster(unsigned addr, unsigned parity) {
    unsigned done;
    do {
        asm volatile(
            "{\n\t.reg .pred p;\n\t"
            "mbarrier.try_wait.parity.acquire.cluster.shared::cta.b64 p, [%1], %2, 0x989680;\n\t"
            "selp.b32 %0, 1, 0, p;\n\t}"
            : "=r"(done) : "r"(addr), "r"(parity) : "memory");
    } while (!done);
}
__device__ __forceinline__ unsigned cluster_rank() {
    unsigned r;
    asm("mov.u32 %0, %%cluster_ctarank;" : "=r"(r));
    return r;
}
__device__ __forceinline__ unsigned mapa_u32(unsigned addr, unsigned rank) {
    unsigned rem;
    asm("mapa.shared::cluster.u32 %0, %1, %2;" : "=r"(rem) : "r"(addr), "r"(rank));
    return rem;
}
__device__ __forceinline__ void st_cluster_f32(unsigned addr, float v) {
    asm volatile("st.shared::cluster.f32 [%0], %1;" :: "r"(addr), "f"(v) : "memory");
}
// plain (non-release) remote arrive — the R4-verified fast path
__device__ __forceinline__ void mbar_arrive_remote(unsigned addr) {
    asm volatile("mbarrier.arrive.shared::cluster.b64 _, [%0];" :: "r"(addr) : "memory");
}
__device__ __forceinline__ void cluster_sync() {
    asm volatile("barrier.cluster.arrive.aligned;" ::: "memory");
    asm volatile("barrier.cluster.wait.aligned;" ::: "memory");
}
__device__ __forceinline__ void bar_arrive_1() {
    asm volatile("bar.arrive 1, %0;" :: "r"(GRU_T) : "memory");
}
__device__ __forceinline__ void bar_sync_1() {
    asm volatile("bar.sync 1, %0;" :: "r"(GRU_T) : "memory");
}
__device__ __forceinline__ float fsigmoid(float x) {
    return __fdividef(1.f, 1.f + __expf(-x));
}
__device__ __forceinline__ float ftanh_fast(float x) {
    return __fdividef(2.f, 1.f + __expf(-2.f * x)) - 1.f;
}

// ---------------- kernel 1: embedding sums -> X -------------------------------
__global__ void embed_kernel(const int* __restrict__ orig,
                             const int* __restrict__ reply,
                             const int* __restrict__ lens,
                             const float* __restrict__ embed) {
    int t = blockIdx.x;
    int e = threadIdx.x;
    if (e >= E) return;
    float acc = 0.f;
    if (t == 0) {
        #pragma unroll 4
        for (int l = 0; l < L0; ++l) {
            int tok = orig[l];
            acc += embed[(long long)tok * E + e];
        }
    } else {
        int r = t - 1;
        int len = lens[r];
        const int* rt = reply + r * LR;
        #pragma unroll 4
        for (int l = 0; l < len; ++l) {
            int tok = rt[l];
            acc += embed[(long long)tok * E + e];
        }
    }
    g_X[t * E + e] = acc;
}

// ---------------- kernel 2: gi GEMMs (both directions) ------------------------
#define TT 32
#define RR 64
#define KC 32
__global__ void gi_kernel(const float* __restrict__ Wf, const float* __restrict__ bf,
                          const float* __restrict__ Wb, const float* __restrict__ bb) {
    int dir = blockIdx.z;
    const float* W    = dir ? Wb : Wf;
    const float* bias = dir ? bb : bf;
    float* out        = dir ? g_gi_b : g_gi_f;
    int t0 = blockIdx.x * TT;
    int r0 = blockIdx.y * RR;

    __shared__ float Xs[TT][KC];
    __shared__ float Ws[RR][KC + 1];

    int tid = threadIdx.x;
    int r  = tid % RR;
    int tg = tid / RR;

    float acc[8];
    #pragma unroll
    for (int j = 0; j < 8; ++j) acc[j] = 0.f;

    for (int kk = 0; kk < E; kk += KC) {
        for (int i = tid; i < RR * KC; i += 256) {
            int rr = i / KC, k = i % KC;
            Ws[rr][k] = (kk + k < E) ? W[(r0 + rr) * E + kk + k] : 0.f;
        }
        for (int i = tid; i < TT * KC; i += 256) {
            int ttl = i / KC, k = i % KC;
            int t = t0 + ttl;
            float v = 0.f;
            if (t < S && kk + k < E) {
                int tsrc = dir ? (S - 1 - t) : t;
                v = g_X[tsrc * E + kk + k];
            }
            Xs[ttl][k] = v;
        }
        __syncthreads();
        #pragma unroll
        for (int k = 0; k < KC; ++k) {
            float wv = Ws[r][k];
            #pragma unroll
            for (int j = 0; j < 8; ++j)
                acc[j] += wv * Xs[tg * 8 + j][k];
        }
        __syncthreads();
    }
    float bv = bias[r0 + r];
    #pragma unroll
    for (int j = 0; j < 8; ++j) {
        int t = t0 + tg * 8 + j;
        if (t < S) out[t * G3 + r0 + r] = acc[j] + bv;
    }
}

// ---------------- kernel 3: GRU recurrence, cluster(8) per direction ----------
// R9 protocol with 8 warps x 12 rows (fewer warps -> lower issue pressure):
// local row lr = w*12 + k (k 0..11); lr maps linearly to (gate = lr>>5,
// dim = lr&31) because rows are assigned consecutively. Lane holds 12 rows x
// 8 cols resident. Per step: mbar wait -> h LDS (f32x2 pairs) -> 48 ffma2 ->
// tree-A (9 shfl, p[0..7] -> lane<8 slot) + tree-B (6 shfl, p[8..11] ->
// lane<4 slot) -> STS row sums (+bias) -> bar.arrive (warps 1-7) / bar.sync
// (warp 0) -> warp0 funnel: gates per lane(dim), register-direct DSMEM publish
// to 8 peers, syncwarp, lanes<8 plain remote arrives. Dbl-buffered h + parity.
__global__ void __launch_bounds__(GRU_T, 1) __cluster_dims__(NC, 1, 1)
gru_kernel(const float* __restrict__ Whh_f, const float* __restrict__ bhh_f,
           const float* __restrict__ Whh_b, const float* __restrict__ bhh_b) {
    int dir = blockIdx.x >> 3;
    unsigned c = cluster_rank();
    const float* Whh = dir ? Whh_b : Whh_f;
    const float* bhh = dir ? bhh_b : bhh_f;
    const float* gi  = dir ? g_gi_b : g_gi_f;
    float* ys        = dir ? g_ys_b : g_ys_f;

    int tid  = threadIdx.x;
    int w    = tid >> 5;        // 0..7
    int lane = tid & 31;
    int base = (int)c * DPC;

    __shared__ __align__(16) float hbuf[2][H];   // double-buffered full h
    __shared__ float s_gh[96];                   // row sums incl. bhh
    __shared__ __align__(8) unsigned long long bars[2];

    unsigned hbuf_u32 = smem_u32(&hbuf[0][0]);
    unsigned bars_u32 = smem_u32(&bars[0]);

    if (tid == 0) { mbar_init(bars_u32, NC); mbar_init(bars_u32 + 8, NC); }
    if (tid < H) hbuf[0][tid] = 0.f;
    __syncthreads();
    cluster_sync();   // peers must not arrive on an uninitialized mbarrier

    // precomputed remote addresses (used by warp 0)
    unsigned remh[NC], remb[NC];
    #pragma unroll
    for (int r = 0; r < NC; ++r) {
        remh[r] = mapa_u32(hbuf_u32, (unsigned)r);
        remb[r] = mapa_u32(bars_u32, (unsigned)r);
    }

    // resident weights: 12 rows x 8 cols per lane, packed f32x2
    unsigned long long w2[12][4];
    #pragma unroll
    for (int k = 0; k < 12; ++k) {
        int lr = w * 12 + k;
        int row = (lr >> 5) * H + base + (lr & 31);
        const float* wr = Whh + (size_t)row * H + lane * 8;
        float4 a = *(const float4*)wr;
        float4 b = *(const float4*)(wr + 4);
        w2[k][0] = pk2(a.x, a.y); w2[k][1] = pk2(a.z, a.w);
        w2[k][2] = pk2(b.x, b.y); w2[k][3] = pk2(b.z, b.w);
    }
    // biases for the row slots this lane owns after the fold reduces
    float bregA, bregB;
    {
        int lrA = w * 12 + (lane & 7);          // tree-A slot
        int rowA = (lrA >> 5) * H + base + (lrA & 31);
        bregA = bhh[rowA];
        int lrB = w * 12 + 8 + (lane & 3);      // tree-B slot
        int rowB = (lrB >> 5) * H + base + (lrB & 31);
        bregB = bhh[rowB];
    }

    // warp0 per-lane gate state (lane = local dim)
    float gir = 0.f, giz = 0.f, gin = 0.f, hold = 0.f;
    if (w == 0) {
        int ii = base + lane;
        gir = gi[ii]; giz = gi[H + ii]; gin = gi[2 * H + ii];   // step 0
    }

    unsigned ph0 = 0, ph1 = 0;
    const unsigned FM = 0xffffffffu;

    for (int t = 0; t < S; ++t) {
        // prefetch gi for step t+1 (warp 0 only; hidden under dot+wait)
        float ngr = 0.f, ngz = 0.f, ngn = 0.f;
        if (w == 0 && t + 1 < S) {
            const float* gp = gi + (t + 1) * G3 + base + lane;
            ngr = __ldg(gp); ngz = __ldg(gp + H); ngn = __ldg(gp + 2 * H);
        }

        // wait for h_t in hbuf[t&1]; t=0 uses zeros
        if (t) {
            if (t & 1) { mbar_wait_cluster(bars_u32 + 8, ph1); ph1 ^= 1; }
            else       { mbar_wait_cluster(bars_u32,     ph0); ph0 ^= 1; }
        }

        // dot: 12 rows x 8 cols per lane; h loaded directly as f32x2 pairs
        const ulonglong2* hp =
            (const ulonglong2*)(&hbuf[t & 1][lane * 8]);
        ulonglong2 ha = hp[0];
        ulonglong2 hb = hp[1];
        unsigned long long h2[4];
        h2[0] = ha.x; h2[1] = ha.y; h2[2] = hb.x; h2[3] = hb.y;

        float p[12];
        #pragma unroll
        for (int k = 0; k < 12; ++k) {
            unsigned long long acc = ffma2(w2[k][0], h2[0], 0ULL);
            acc = ffma2(w2[k][1], h2[1], acc);
            acc = ffma2(w2[k][2], h2[2], acc);
            acc = ffma2(w2[k][3], h2[3], acc);
            p[k] = unpk_sum(acc);
        }

        bool b0 = (lane & 1), b1 = (lane & 2), b2 = (lane & 4);

        // tree A: p[0..7] -> uA = full sum of row slot (lane&7)
        float q0, q1, q2, q3, r0v, r1v, uA;
        { float v = b0 ? p[0] : p[1]; float sx = __shfl_xor_sync(FM, v, 1);
          q0 = (b0 ? p[1] : p[0]) + sx; }
        { float v = b0 ? p[2] : p[3]; float sx = __shfl_xor_sync(FM, v, 1);
          q1 = (b0 ? p[3] : p[2]) + sx; }
        { float v = b0 ? p[4] : p[5]; float sx = __shfl_xor_sync(FM, v, 1);
          q2 = (b0 ? p[5] : p[4]) + sx; }
        { float v = b0 ? p[6] : p[7]; float sx = __shfl_xor_sync(FM, v, 1);
          q3 = (b0 ? p[7] : p[6]) + sx; }
        { float v = b1 ? q0 : q1; float sx = __shfl_xor_sync(FM, v, 2);
          r0v = (b1 ? q1 : q0) + sx; }
        { float v = b1 ? q2 : q3; float sx = __shfl_xor_sync(FM, v, 2);
          r1v = (b1 ? q3 : q2) + sx; }
        { float v = b2 ? r0v : r1v; float sx = __shfl_xor_sync(FM, v, 4);
          uA = (b2 ? r1v : r0v) + sx; }
        uA += __shfl_xor_sync(FM, uA, 8);
        uA += __shfl_xor_sync(FM, uA, 16);

        // tree B: p[8..11] -> uB = full sum of row slot 8+(lane&3)
        float uB;
        { float vb0, vb1;
          { float v = b0 ? p[8] : p[9]; float sx = __shfl_xor_sync(FM, v, 1);
            vb0 = (b0 ? p[9] : p[8]) + sx; }
          { float v = b0 ? p[10] : p[11]; float sx = __shfl_xor_sync(FM, v, 1);
            vb1 = (b0 ? p[11] : p[10]) + sx; }
          { float v = b1 ? vb0 : vb1; float sx = __shfl_xor_sync(FM, v, 2);
            uB = (b1 ? vb1 : vb0) + sx; }
          uB += __shfl_xor_sync(FM, uB, 4);
          uB += __shfl_xor_sync(FM, uB, 8);
          uB += __shfl_xor_sync(FM, uB, 16);
        }

        if (lane < 8) s_gh[w * 12 + lane] = uA + bregA;
        if (lane < 4) s_gh[w * 12 + 8 + lane] = uB + bregB;

        if (w != 0) {
            bar_arrive_1();        // non-blocking; next stop: mbar wait t+1
        } else {
            bar_sync_1();          // wait for all 8 warps' STS (BAR drains STS)
            // gates: lane = local dim
            float ghr = s_gh[lane];
            float ghz = s_gh[32 + lane];
            float ghn = s_gh[64 + lane];
            float rr = fsigmoid(gir + ghr);
            float zz = fsigmoid(giz + ghz);
            float nn = ftanh_fast(gin + rr * ghn);
            float hn = (1.f - zz) * nn + zz * hold;
            hold = hn;

            // publish h_{t+1} to all 8 CTAs (register-direct DSMEM stores)
            if (t + 1 < S) {
                unsigned off = (unsigned)(((t + 1) & 1) * (H * 4) + (base + lane) * 4);
                #pragma unroll
                for (int r = 0; r < NC; ++r)
                    st_cluster_f32(remh[r] + off, hn);
                __syncwarp();
                if (lane < NC)
                    mbar_arrive_remote(remb[lane] + ((t + 1) & 1) * 8);
            }

            int trow = dir ? (S - 1 - t) : t;
            ys[trow * H + base + lane] = hn;
            gir = ngr; giz = ngz; gin = ngn;
        }
    }
    cluster_sync();
}

// ---------------- kernel 4: output projection --------------------------------
#define OTT 16
__global__ void outproj_kernel(const float* __restrict__ Wl,
                               const float* __restrict__ bl,
                               float* __restrict__ outbuf) {
    int t0 = blockIdx.x * OTT;
    int j0 = blockIdx.y * RR;
    __shared__ float As[OTT][KC];
    __shared__ float Ws[RR][KC + 1];
    int tid = threadIdx.x;
    int r  = tid % RR;
    int tg = tid / RR;
    float acc[4];
    #pragma unroll
    for (int j = 0; j < 4; ++j) acc[j] = 0.f;

    for (int kk = 0; kk < 2 * H; kk += KC) {
        const float* ysrc = (kk < H) ? g_ys_f : g_ys_b;
        int kbase = (kk < H) ? kk : (kk - H);
        for (int i = tid; i < RR * KC; i += 256) {
            int rr = i / KC, k = i % KC;
            Ws[rr][k] = Wl[(j0 + rr) * (2 * H) + kk + k];
        }
        for (int i = tid; i < OTT * KC; i += 256) {
            int ttl = i / KC, k = i % KC;
            int t = t0 + ttl;
            As[ttl][k] = (t < S) ? ysrc[t * H + kbase + k] : 0.f;
        }
        __syncthreads();
        #pragma unroll
        for (int k = 0; k < KC; ++k) {
            float wv = Ws[r][k];
            #pragma unroll
            for (int j = 0; j < 4; ++j)
                acc[j] += wv * As[tg * 4 + j][k];
        }
        __syncthreads();
    }
    float bv = bl[j0 + r];
    #pragma unroll
    for (int j = 0; j < 4; ++j) {
        int t = t0 + tg * 4 + j;
        if (t < S) outbuf[t * H + j0 + r] = acc[j] + bv;
    }
}

// ---------------- kernel 5: attention + final head (single block) -------------
__global__ void attn_kernel(const float* __restrict__ outbuf,
                            const float* __restrict__ Wo,
                            const float* __restrict__ bo,
                            const float* __restrict__ label,
                            float* __restrict__ tail) {
    __shared__ float s_hsum[H];
    __shared__ float s_w[S];
    __shared__ float s_red[32];
    __shared__ float s_ctx[4][H];

    int tid = threadIdx.x;
    int wp  = tid >> 5;
    int ln  = tid & 31;

    if (tid < H) s_hsum[tid] = g_ys_f[(S - 1) * H + tid] + g_ys_b[tid];
    __syncthreads();

    for (int t = wp; t < S; t += 32) {
        const float* o = outbuf + t * H;
        float s = 0.f;
        #pragma unroll
        for (int k = ln; k < H; k += 32) s += o[k] * s_hsum[k];
        s += __shfl_down_sync(0xffffffffu, s, 16);
        s += __shfl_down_sync(0xffffffffu, s, 8);
        s += __shfl_down_sync(0xffffffffu, s, 4);
        s += __shfl_down_sync(0xffffffffu, s, 2);
        s += __shfl_down_sync(0xffffffffu, s, 1);
        if (ln == 0) s_w[t] = s;
    }
    __syncthreads();

    float m = -CUDART_INF_F;
    for (int t = tid; t < S; t += 1024) m = fmaxf(m, s_w[t]);
    for (int off = 16; off >= 1; off >>= 1)
        m = fmaxf(m, __shfl_down_sync(0xffffffffu, m, off));
    if (ln == 0) s_red[wp] = m;
    __syncthreads();
    if (tid < 32) {
        float mm = s_red[tid];
        for (int off = 16; off >= 1; off >>= 1)
            mm = fmaxf(mm, __shfl_down_sync(0xffffffffu, mm, off));
        if (tid == 0) s_red[0] = mm;
    }
    __syncthreads();
    float M = s_red[0];
    __syncthreads();

    float lsum = 0.f;
    for (int t = tid; t < S; t += 1024) {
        float e = expf(s_w[t] - M);
        s_w[t] = e;
        lsum += e;
    }
    for (int off = 16; off >= 1; off >>= 1)
        lsum += __shfl_down_sync(0xffffffffu, lsum, off);
    if (ln == 0) s_red[wp] = lsum;
    __syncthreads();
    if (tid < 32) {
        float ss = s_red[tid];
        for (int off = 16; off >= 1; off >>= 1)
            ss += __shfl_down_sync(0xffffffffu, ss, off);
        if (tid == 0) s_red[0] = ss;
    }
    __syncthreads();
    float SUM = s_red[0];

    int j    = tid & 255;
    int part = tid >> 8;
    float cacc = 0.f;
    #pragma unroll 4
    for (int t = part; t < S; t += 4) cacc += s_w[t] * outbuf[t * H + j];
    s_ctx[part][j] = cacc;
    __syncthreads();

    if (tid < H) {
        float cj = (s_ctx[0][tid] + s_ctx[1][tid] + s_ctx[2][tid] + s_ctx[3][tid]) / SUM;
        s_hsum[tid] = cj * Wo[tid];
    }
    __syncthreads();

    if (tid < 32) {
        float a = 0.f;
        #pragma unroll
        for (int q = 0; q < 8; ++q) a += s_hsum[tid + q * 32];
        for (int off = 16; off >= 1; off >>= 1)
            a += __shfl_down_sync(0xffffffffu, a, off);
        if (tid == 0) {
            float res = 1.f / (1.f + expf(-(a + bo[0])));
            float d = label[0] - res;
            tail[0] = d * d;
            tail[1] = res;
        }
    }
}

// ---------------- launch ------------------------------------------------------
extern "C" void kernel_launch(void* const* d_in, const int* in_sizes, int n_in,
                              void* d_out, int out_size) {
    const int*   orig   = (const int*)d_in[0];
    const int*   reply  = (const int*)d_in[1];
    const int*   lens   = (const int*)d_in[2];
    const float* label  = (const float*)d_in[3];
    const float* embed  = (const float*)d_in[4];
    const float* Wih_f  = (const float*)d_in[5];
    const float* Whh_f  = (const float*)d_in[6];
    const float* bih_f  = (const float*)d_in[7];
    const float* bhh_f  = (const float*)d_in[8];
    const float* Wih_b  = (const float*)d_in[9];
    const float* Whh_b  = (const float*)d_in[10];
    const float* bih_b  = (const float*)d_in[11];
    const float* bhh_b  = (const float*)d_in[12];
    const float* Wl     = (const float*)d_in[13];
    const float* bl     = (const float*)d_in[14];
    const float* Wo     = (const float*)d_in[15];
    const float* bo     = (const float*)d_in[16];
    float* out = (float*)d_out;

    embed_kernel<<<S, 320>>>(orig, reply, lens, embed);

    dim3 gi_grid((S + TT - 1) / TT, G3 / RR, 2);
    gi_kernel<<<gi_grid, 256>>>(Wih_f, bih_f, Wih_b, bih_b);

    gru_kernel<<<2 * NC, GRU_T>>>(Whh_f, bhh_f, Whh_b, bhh_b);

    dim3 op_grid((S + OTT - 1) / OTT, H / RR);   // 129 x 4
    outproj_kernel<<<op_grid, 256>>>(Wl, bl, out);

    attn_kernel<<<1, 1024>>>(out, Wo, bo, label, out + S * H);
}

// round 13
// speedup vs baseline: 1.8331x; 1.0910x over previous
#include <cuda_runtime.h>
#include <math_constants.h>

#define V  50000
#define E  300
#define H  256
#define R  2048
#define L0 128
#define LR 64
#define S  2049          // 1 + R
#define G3 768           // 3*H

#define NC     8         // CTAs per cluster (one cluster per direction)
#define DPC    32        // h-dims per CTA
#define GRU_T  384       // 12 warps x 8 rows = 96 rows per CTA

// ---------------- scratch (device globals; no allocation allowed) -------------
__device__ float g_X[S * E];
__device__ float g_gi_f[S * G3];
__device__ float g_gi_b[S * G3];
__device__ float g_ys_f[S * H];
__device__ float g_ys_b[S * H];

// ---------------- small PTX helpers ------------------------------------------
__device__ __forceinline__ unsigned long long pk2(float lo, float hi) {
    unsigned long long r;
    asm("mov.b64 %0, {%1, %2};" : "=l"(r) : "f"(lo), "f"(hi));
    return r;
}
__device__ __forceinline__ float unpk_sum(unsigned long long v) {
    float a, b;
    asm("mov.b64 {%0, %1}, %2;" : "=f"(a), "=f"(b) : "l"(v));
    return a + b;
}
__device__ __forceinline__ unsigned long long ffma2(unsigned long long a,
                                                    unsigned long long b,
                                                    unsigned long long c) {
    unsigned long long d;
    asm("fma.rn.f32x2 %0, %1, %2, %3;" : "=l"(d) : "l"(a), "l"(b), "l"(c));
    return d;
}
__device__ __forceinline__ unsigned smem_u32(const void* p) {
    return (unsigned)__cvta_generic_to_shared(p);
}
__device__ __forceinline__ void mbar_init(unsigned addr, unsigned count) {
    asm volatile("mbarrier.init.shared.b64 [%0], %1;" :: "r"(addr), "r"(count) : "memory");
}
__device__ __forceinline__ void mbar_wait_cluster(unsigned addr, unsigned parity) {
    unsigned done;
    do {
        asm volatile(
            "{\n\t.reg .pred p;\n\t"
            "mbarrier.try_wait.parity.acquire.cluster.shared::cta.b64 p, [%1], %2, 0x989680;\n\t"
            "selp.b32 %0, 1, 0, p;\n\t}"
            : "=r"(done) : "r"(addr), "r"(parity) : "memory");
    } while (!done);
}
__device__ __forceinline__ unsigned cluster_rank() {
    unsigned r;
    asm("mov.u32 %0, %%cluster_ctarank;" : "=r"(r));
    return r;
}
__device__ __forceinline__ unsigned mapa_u32(unsigned addr, unsigned rank) {
    unsigned rem;
    asm("mapa.shared::cluster.u32 %0, %1, %2;" : "=r"(rem) : "r"(addr), "r"(rank));
    return rem;
}
__device__ __forceinline__ void st_cluster_f32(unsigned addr, float v) {
    asm volatile("st.shared::cluster.f32 [%0], %1;" :: "r"(addr), "f"(v) : "memory");
}
// plain (non-release) remote arrive — the R4-verified fast path
__device__ __forceinline__ void mbar_arrive_remote(unsigned addr) {
    asm volatile("mbarrier.arrive.shared::cluster.b64 _, [%0];" :: "r"(addr) : "memory");
}
__device__ __forceinline__ void cluster_sync() {
    asm volatile("barrier.cluster.arrive.aligned;" ::: "memory");
    asm volatile("barrier.cluster.wait.aligned;" ::: "memory");
}
__device__ __forceinline__ void bar_arrive_1() {
    asm volatile("bar.arrive 1, %0;" :: "r"(GRU_T) : "memory");
}
__device__ __forceinline__ void bar_sync_1() {
    asm volatile("bar.sync 1, %0;" :: "r"(GRU_T) : "memory");
}
// HW tanh (sm_75+): single special-function op, ~16 cyc
__device__ __forceinline__ float tanh_hw(float x) {
    float y;
    asm("tanh.approx.f32 %0, %1;" : "=f"(y) : "f"(x));
    return y;
}
// sigmoid via HW tanh: sigmoid(x) = 0.5*tanh(x/2) + 0.5  (FMUL+TANH+FFMA)
__device__ __forceinline__ float fsigmoid_hw(float x) {
    return fmaf(0.5f, tanh_hw(0.5f * x), 0.5f);
}
__device__ __forceinline__ float fsigmoid(float x) {
    return __fdividef(1.f, 1.f + __expf(-x));
}

// ---------------- kernel 1: embedding sums -> X -------------------------------
__global__ void embed_kernel(const int* __restrict__ orig,
                             const int* __restrict__ reply,
                             const int* __restrict__ lens,
                             const float* __restrict__ embed) {
    int t = blockIdx.x;
    int e = threadIdx.x;
    if (e >= E) return;
    float acc = 0.f;
    if (t == 0) {
        #pragma unroll 4
        for (int l = 0; l < L0; ++l) {
            int tok = orig[l];
            acc += embed[(long long)tok * E + e];
        }
    } else {
        int r = t - 1;
        int len = lens[r];
        const int* rt = reply + r * LR;
        #pragma unroll 4
        for (int l = 0; l < len; ++l) {
            int tok = rt[l];
            acc += embed[(long long)tok * E + e];
        }
    }
    g_X[t * E + e] = acc;
}

// ---------------- kernel 2: gi GEMMs (both directions) ------------------------
#define TT 32
#define RR 64
#define KC 32
__global__ void gi_kernel(const float* __restrict__ Wf, const float* __restrict__ bf,
                          const float* __restrict__ Wb, const float* __restrict__ bb) {
    int dir = blockIdx.z;
    const float* W    = dir ? Wb : Wf;
    const float* bias = dir ? bb : bf;
    float* out        = dir ? g_gi_b : g_gi_f;
    int t0 = blockIdx.x * TT;
    int r0 = blockIdx.y * RR;

    __shared__ float Xs[TT][KC];
    __shared__ float Ws[RR][KC + 1];

    int tid = threadIdx.x;
    int r  = tid % RR;
    int tg = tid / RR;

    float acc[8];
    #pragma unroll
    for (int j = 0; j < 8; ++j) acc[j] = 0.f;

    for (int kk = 0; kk < E; kk += KC) {
        for (int i = tid; i < RR * KC; i += 256) {
            int rr = i / KC, k = i % KC;
            Ws[rr][k] = (kk + k < E) ? W[(r0 + rr) * E + kk + k] : 0.f;
        }
        for (int i = tid; i < TT * KC; i += 256) {
            int ttl = i / KC, k = i % KC;
            int t = t0 + ttl;
            float v = 0.f;
            if (t < S && kk + k < E) {
                int tsrc = dir ? (S - 1 - t) : t;
                v = g_X[tsrc * E + kk + k];
            }
            Xs[ttl][k] = v;
        }
        __syncthreads();
        #pragma unroll
        for (int k = 0; k < KC; ++k) {
            float wv = Ws[r][k];
            #pragma unroll
            for (int j = 0; j < 8; ++j)
                acc[j] += wv * Xs[tg * 8 + j][k];
        }
        __syncthreads();
    }
    float bv = bias[r0 + r];
    #pragma unroll
    for (int j = 0; j < 8; ++j) {
        int t = t0 + tg * 8 + j;
        if (t < S) out[t * G3 + r0 + r] = acc[j] + bv;
    }
}

// ---------------- kernel 3: GRU recurrence, cluster(8) per direction ----------
// EXACT R9 structure (verified 1570us); ONLY change: gate activations use the
// HW tanh.approx path (sigmoid = 0.5*tanh(x/2)+0.5, n = tanh directly),
// shortening the warp-0 funnel's serial chain by ~50 cyc/step.
__global__ void __launch_bounds__(GRU_T, 1) __cluster_dims__(NC, 1, 1)
gru_kernel(const float* __restrict__ Whh_f, const float* __restrict__ bhh_f,
           const float* __restrict__ Whh_b, const float* __restrict__ bhh_b) {
    int dir = blockIdx.x >> 3;
    unsigned c = cluster_rank();
    const float* Whh = dir ? Whh_b : Whh_f;
    const float* bhh = dir ? bhh_b : bhh_f;
    const float* gi  = dir ? g_gi_b : g_gi_f;
    float* ys        = dir ? g_ys_b : g_ys_f;

    int tid  = threadIdx.x;
    int w    = tid >> 5;        // 0..11
    int lane = tid & 31;
    int base = (int)c * DPC;

    __shared__ __align__(16) float hbuf[2][H];   // double-buffered full h
    __shared__ float s_gh[96];                   // row sums incl. bhh
    __shared__ __align__(8) unsigned long long bars[2];

    unsigned hbuf_u32 = smem_u32(&hbuf[0][0]);
    unsigned bars_u32 = smem_u32(&bars[0]);

    if (tid == 0) { mbar_init(bars_u32, NC); mbar_init(bars_u32 + 8, NC); }
    if (tid < H) hbuf[0][tid] = 0.f;
    __syncthreads();
    cluster_sync();   // peers must not arrive on an uninitialized mbarrier

    // precomputed remote addresses (used by warp 0)
    unsigned remh[NC], remb[NC];
    #pragma unroll
    for (int r = 0; r < NC; ++r) {
        remh[r] = mapa_u32(hbuf_u32, (unsigned)r);
        remb[r] = mapa_u32(bars_u32, (unsigned)r);
    }

    // resident weights: 8 rows x 8 cols per lane, packed f32x2
    unsigned long long w2[8][4];
    #pragma unroll
    for (int k = 0; k < 8; ++k) {
        int lr = w * 8 + k;
        int row = (lr >> 5) * H + base + (lr & 31);
        const float* wr = Whh + (size_t)row * H + lane * 8;
        float4 a = *(const float4*)wr;
        float4 b = *(const float4*)(wr + 4);
        w2[k][0] = pk2(a.x, a.y); w2[k][1] = pk2(a.z, a.w);
        w2[k][2] = pk2(b.x, b.y); w2[k][3] = pk2(b.z, b.w);
    }
    // bias for the row slot this lane owns after the fold reduce
    float breg;
    {
        int lrb = w * 8 + (lane & 7);
        int rowb = (lrb >> 5) * H + base + (lrb & 31);
        breg = bhh[rowb];
    }

    // warp0 per-lane gate state (lane = local dim)
    float gir = 0.f, giz = 0.f, gin = 0.f, hold = 0.f;
    if (w == 0) {
        int ii = base + lane;
        gir = gi[ii]; giz = gi[H + ii]; gin = gi[2 * H + ii];   // step 0
    }

    unsigned ph0 = 0, ph1 = 0;
    const unsigned FM = 0xffffffffu;

    for (int t = 0; t < S; ++t) {
        // prefetch gi for step t+1 (warp 0 only; hidden under dot+wait)
        float ngr = 0.f, ngz = 0.f, ngn = 0.f;
        if (w == 0 && t + 1 < S) {
            const float* gp = gi + (t + 1) * G3 + base + lane;
            ngr = __ldg(gp); ngz = __ldg(gp + H); ngn = __ldg(gp + 2 * H);
        }

        // wait for h_t in hbuf[t&1]; t=0 uses zeros
        if (t) {
            if (t & 1) { mbar_wait_cluster(bars_u32 + 8, ph1); ph1 ^= 1; }
            else       { mbar_wait_cluster(bars_u32,     ph0); ph0 ^= 1; }
        }

        // dot: 8 rows x 8 cols per lane; h loaded directly as f32x2 pairs
        const ulonglong2* hp =
            (const ulonglong2*)(&hbuf[t & 1][lane * 8]);
        ulonglong2 ha = hp[0];
        ulonglong2 hb = hp[1];
        unsigned long long h2[4];
        h2[0] = ha.x; h2[1] = ha.y; h2[2] = hb.x; h2[3] = hb.y;

        float p[8];
        #pragma unroll
        for (int k = 0; k < 8; ++k) {
            unsigned long long acc = ffma2(w2[k][0], h2[0], 0ULL);
            acc = ffma2(w2[k][1], h2[1], acc);
            acc = ffma2(w2[k][2], h2[2], acc);
            acc = ffma2(w2[k][3], h2[3], acc);
            p[k] = unpk_sum(acc);
        }

        // fold reduce: 8 values over 32 lanes -> lane l<8 holds row 8w+l
        bool b0 = (lane & 1), b1 = (lane & 2), b2 = (lane & 4);
        float q0, q1, q2, q3, r0v, r1v, u;
        { float v = b0 ? p[0] : p[1]; float sx = __shfl_xor_sync(FM, v, 1);
          q0 = (b0 ? p[1] : p[0]) + sx; }
        { float v = b0 ? p[2] : p[3]; float sx = __shfl_xor_sync(FM, v, 1);
          q1 = (b0 ? p[3] : p[2]) + sx; }
        { float v = b0 ? p[4] : p[5]; float sx = __shfl_xor_sync(FM, v, 1);
          q2 = (b0 ? p[5] : p[4]) + sx; }
        { float v = b0 ? p[6] : p[7]; float sx = __shfl_xor_sync(FM, v, 1);
          q3 = (b0 ? p[7] : p[6]) + sx; }
        { float v = b1 ? q0 : q1; float sx = __shfl_xor_sync(FM, v, 2);
          r0v = (b1 ? q1 : q0) + sx; }
        { float v = b1 ? q2 : q3; float sx = __shfl_xor_sync(FM, v, 2);
          r1v = (b1 ? q3 : q2) + sx; }
        { float v = b2 ? r0v : r1v; float sx = __shfl_xor_sync(FM, v, 4);
          u = (b2 ? r1v : r0v) + sx; }
        u += __shfl_xor_sync(FM, u, 8);
        u += __shfl_xor_sync(FM, u, 16);
        if (lane < 8) s_gh[w * 8 + lane] = u + breg;   // gh row incl. bias

        if (w != 0) {
            bar_arrive_1();        // non-blocking; next stop: mbar wait t+1
        } else {
            bar_sync_1();          // wait for all 12 warps' STS (BAR drains STS)
            // gates: lane = local dim — HW tanh.approx path (short chain)
            float ghr = s_gh[lane];
            float ghz = s_gh[32 + lane];
            float ghn = s_gh[64 + lane];
            float rr = fsigmoid_hw(gir + ghr);
            float zz = fsigmoid_hw(giz + ghz);
            float nn = tanh_hw(fmaf(rr, ghn, gin));
            float hn = (1.f - zz) * nn + zz * hold;
            hold = hn;

            // publish h_{t+1} to all 8 CTAs (register-direct DSMEM stores)
            if (t + 1 < S) {
                unsigned off = (unsigned)(((t + 1) & 1) * (H * 4) + (base + lane) * 4);
                #pragma unroll
                for (int r = 0; r < NC; ++r)
                    st_cluster_f32(remh[r] + off, hn);
                __syncwarp();
                if (lane < NC)
                    mbar_arrive_remote(remb[lane] + ((t + 1) & 1) * 8);
            }

            int trow = dir ? (S - 1 - t) : t;
            ys[trow * H + base + lane] = hn;
            gir = ngr; giz = ngz; gin = ngn;
        }
    }
    cluster_sync();
}

// ---------------- kernel 4: output projection --------------------------------
#define OTT 16
__global__ void outproj_kernel(const float* __restrict__ Wl,
                               const float* __restrict__ bl,
                               float* __restrict__ outbuf) {
    int t0 = blockIdx.x * OTT;
    int j0 = blockIdx.y * RR;
    __shared__ float As[OTT][KC];
    __shared__ float Ws[RR][KC + 1];
    int tid = threadIdx.x;
    int r  = tid % RR;
    int tg = tid / RR;
    float acc[4];
    #pragma unroll
    for (int j = 0; j < 4; ++j) acc[j] = 0.f;

    for (int kk = 0; kk < 2 * H; kk += KC) {
        const float* ysrc = (kk < H) ? g_ys_f : g_ys_b;
        int kbase = (kk < H) ? kk : (kk - H);
        for (int i = tid; i < RR * KC; i += 256) {
            int rr = i / KC, k = i % KC;
            Ws[rr][k] = Wl[(j0 + rr) * (2 * H) + kk + k];
        }
        for (int i = tid; i < OTT * KC; i += 256) {
            int ttl = i / KC, k = i % KC;
            int t = t0 + ttl;
            As[ttl][k] = (t < S) ? ysrc[t * H + kbase + k] : 0.f;
        }
        __syncthreads();
        #pragma unroll
        for (int k = 0; k < KC; ++k) {
            float wv = Ws[r][k];
            #pragma unroll
            for (int j = 0; j < 4; ++j)
                acc[j] += wv * As[tg * 4 + j][k];
        }
        __syncthreads();
    }
    float bv = bl[j0 + r];
    #pragma unroll
    for (int j = 0; j < 4; ++j) {
        int t = t0 + tg * 4 + j;
        if (t < S) outbuf[t * H + j0 + r] = acc[j] + bv;
    }
}

// ---------------- kernel 5: attention + final head (single block) -------------
__global__ void attn_kernel(const float* __restrict__ outbuf,
                            const float* __restrict__ Wo,
                            const float* __restrict__ bo,
                            const float* __restrict__ label,
                            float* __restrict__ tail) {
    __shared__ float s_hsum[H];
    __shared__ float s_w[S];
    __shared__ float s_red[32];
    __shared__ float s_ctx[4][H];

    int tid = threadIdx.x;
    int wp  = tid >> 5;
    int ln  = tid & 31;

    if (tid < H) s_hsum[tid] = g_ys_f[(S - 1) * H + tid] + g_ys_b[tid];
    __syncthreads();

    for (int t = wp; t < S; t += 32) {
        const float* o = outbuf + t * H;
        float s = 0.f;
        #pragma unroll
        for (int k = ln; k < H; k += 32) s += o[k] * s_hsum[k];
        s += __shfl_down_sync(0xffffffffu, s, 16);
        s += __shfl_down_sync(0xffffffffu, s, 8);
        s += __shfl_down_sync(0xffffffffu, s, 4);
        s += __shfl_down_sync(0xffffffffu, s, 2);
        s += __shfl_down_sync(0xffffffffu, s, 1);
        if (ln == 0) s_w[t] = s;
    }
    __syncthreads();

    float m = -CUDART_INF_F;
    for (int t = tid; t < S; t += 1024) m = fmaxf(m, s_w[t]);
    for (int off = 16; off >= 1; off >>= 1)
        m = fmaxf(m, __shfl_down_sync(0xffffffffu, m, off));
    if (ln == 0) s_red[wp] = m;
    __syncthreads();
    if (tid < 32) {
        float mm = s_red[tid];
        for (int off = 16; off >= 1; off >>= 1)
            mm = fmaxf(mm, __shfl_down_sync(0xffffffffu, mm, off));
        if (tid == 0) s_red[0] = mm;
    }
    __syncthreads();
    float M = s_red[0];
    __syncthreads();

    float lsum = 0.f;
    for (int t = tid; t < S; t += 1024) {
        float e = expf(s_w[t] - M);
        s_w[t] = e;
        lsum += e;
    }
    for (int off = 16; off >= 1; off >>= 1)
        lsum += __shfl_down_sync(0xffffffffu, lsum, off);
    if (ln == 0) s_red[wp] = lsum;
    __syncthreads();
    if (tid < 32) {
        float ss = s_red[tid];
        for (int off = 16; off >= 1; off >>= 1)
            ss += __shfl_down_sync(0xffffffffu, ss, off);
        if (tid == 0) s_red[0] = ss;
    }
    __syncthreads();
    float SUM = s_red[0];

    int j    = tid & 255;
    int part = tid >> 8;
    float cacc = 0.f;
    #pragma unroll 4
    for (int t = part; t < S; t += 4) cacc += s_w[t] * outbuf[t * H + j];
    s_ctx[part][j] = cacc;
    __syncthreads();

    if (tid < H) {
        float cj = (s_ctx[0][tid] + s_ctx[1][tid] + s_ctx[2][tid] + s_ctx[3][tid]) / SUM;
        s_hsum[tid] = cj * Wo[tid];
    }
    __syncthreads();

    if (tid < 32) {
        float a = 0.f;
        #pragma unroll
        for (int q = 0; q < 8; ++q) a += s_hsum[tid + q * 32];
        for (int off = 16; off >= 1; off >>= 1)
            a += __shfl_down_sync(0xffffffffu, a, off);
        if (tid == 0) {
            float res = 1.f / (1.f + expf(-(a + bo[0])));
            float d = label[0] - res;
            tail[0] = d * d;
            tail[1] = res;
        }
    }
}

// ---------------- launch ------------------------------------------------------
extern "C" void kernel_launch(void* const* d_in, const int* in_sizes, int n_in,
                              void* d_out, int out_size) {
    const int*   orig   = (const int*)d_in[0];
    const int*   reply  = (const int*)d_in[1];
    const int*   lens   = (const int*)d_in[2];
    const float* label  = (const float*)d_in[3];
    const float* embed  = (const float*)d_in[4];
    const float* Wih_f  = (const float*)d_in[5];
    const float* Whh_f  = (const float*)d_in[6];
    const float* bih_f  = (const float*)d_in[7];
    const float* bhh_f  = (const float*)d_in[8];
    const float* Wih_b  = (const float*)d_in[9];
    const float* Whh_b  = (const float*)d_in[10];
    const float* bih_b  = (const float*)d_in[11];
    const float* bhh_b  = (const float*)d_in[12];
    const float* Wl     = (const float*)d_in[13];
    const float* bl     = (const float*)d_in[14];
    const float* Wo     = (const float*)d_in[15];
    const float* bo     = (const float*)d_in[16];
    float* out = (float*)d_out;

    embed_kernel<<<S, 320>>>(orig, reply, lens, embed);

    dim3 gi_grid((S + TT - 1) / TT, G3 / RR, 2);
    gi_kernel<<<gi_grid, 256>>>(Wih_f, bih_f, Wih_b, bih_b);

    gru_kernel<<<2 * NC, GRU_T>>>(Whh_f, bhh_f, Whh_b, bhh_b);

    dim3 op_grid((S + OTT - 1) / OTT, H / RR);   // 129 x 4
    outproj_kernel<<<op_grid, 256>>>(Wl, bl, out);

    attn_kernel<<<1, 1024>>>(out, Wo, bo, label, out + S * H);
}